// round 1
// baseline (speedup 1.0000x reference)
#include <cuda_runtime.h>
#include <cuda_bf16.h>

// Problem constants (fixed shapes from reference)
constexpr int B = 256;
constexpr int P = 1024;
constexpr int G = 128;
constexpr float DIST_T2 = 500.0f * 500.0f;   // compare squared distance
constexpr float BBOX_THRESH = 0.1f;

__global__ __launch_bounds__(256, 8) void proposal_kernel(
    const float* __restrict__ topk_index,    // [B,P,3]
    const float* __restrict__ topk_confs,    // [B,P]
    const float* __restrict__ bbox_preds,    // [B,P,2]
    const float* __restrict__ gt_3d,         // [B,G,3]
    const float* __restrict__ gt_bbox,       // [B,G,2]
    const int*   __restrict__ num_person,    // [B]
    float*       __restrict__ out)           // [B,P,7]
{
    __shared__ float sgx[G], sgy[G], sgz[G];
    __shared__ float sb0[G], sb1[G];

    const int b   = blockIdx.y;
    const int tid = threadIdx.x;

    // Stage this batch's GT data into shared memory (broadcast reads later).
    if (tid < G) {
        const float* g3 = gt_3d + ((size_t)b * G + tid) * 3;
        sgx[tid] = g3[0];
        sgy[tid] = g3[1];
        sgz[tid] = g3[2];
        const float* gb = gt_bbox + ((size_t)b * G + tid) * 2;
        sb0[tid] = gb[0];
        sb1[tid] = gb[1];
    }
    const int n = num_person[b];   // uniform per CTA -> no divergence
    __syncthreads();

    const int p = blockIdx.x * 256 + tid;
    const size_t bp = (size_t)b * P + p;

    const float x = topk_index[bp * 3 + 0];
    const float y = topk_index[bp * 3 + 1];
    const float z = topk_index[bp * 3 + 2];

    // Argmin over valid GT slots; strict < keeps first-index tie-break (JAX argmin).
    float best = 3.402823466e38f;
    int   bg   = 0;
    #pragma unroll 4
    for (int g = 0; g < n; ++g) {
        const float dx = x - sgx[g];
        const float dy = y - sgy[g];
        const float dz = z - sgz[g];
        const float d2 = fmaf(dx, dx, fmaf(dy, dy, dz * dz));
        if (d2 < best) { best = d2; bg = g; }
    }

    // dist > 500  <=>  d2 > 500^2 (sqrt is monotone; compare-exact)
    const float p2g = (best > DIST_T2) ? -1.0f : (float)bg;

    const float mb0 = sb0[bg];
    const float mb1 = sb1[bg];
    const float bp0 = bbox_preds[bp * 2 + 0];
    const float bp1 = bbox_preds[bp * 2 + 1];

    const bool cond = (p2g >= 0.0f) &&
                      ((bp0 < mb0 - BBOX_THRESH) || (bp1 < mb1 - BBOX_THRESH));
    const float o5 = cond ? mb0 : bp0;
    const float o6 = cond ? mb1 : bp1;
    const float conf = topk_confs[bp];

    float* o = out + bp * 7;
    o[0] = x;
    o[1] = y;
    o[2] = z;
    o[3] = p2g;
    o[4] = conf;
    o[5] = o5;
    o[6] = o6;
}

extern "C" void kernel_launch(void* const* d_in, const int* in_sizes, int n_in,
                              void* d_out, int out_size) {
    const float* topk_index  = (const float*)d_in[0];  // [B,P,3]
    const float* topk_confs  = (const float*)d_in[1];  // [B,P]
    const float* bbox_preds  = (const float*)d_in[2];  // [B,P,2]
    const float* gt_3d       = (const float*)d_in[3];  // [B,G,3]
    const float* gt_bbox     = (const float*)d_in[4];  // [B,G,2]
    const int*   num_person  = (const int*)  d_in[5];  // [B]
    float*       out         = (float*)d_out;          // [B,P,7]

    dim3 grid(P / 256, B);
    proposal_kernel<<<grid, 256>>>(topk_index, topk_confs, bbox_preds,
                                   gt_3d, gt_bbox, num_person, out);
}